// round 7
// baseline (speedup 1.0000x reference)
#include <cuda_runtime.h>
#include <math.h>
#include <stdint.h>

// ---------------- problem constants ----------------
#define BATCH 64
#define HS_   56
#define CC    128
#define NH_   4
#define HID_  512
#define PIX   (BATCH*HS_*HS_)      // 200704
#define M1_   PIX                  // window-token rows
#define M2_   (BATCH*28*28)        // 50176 merged rows

// weight scratch offsets (floats)
#define WOFF_QKV   0
#define WOFF_PROJ  49152
#define WOFF_FC1   65536
#define WOFF_FC2   131072
#define WOFF_MRG   196608
#define WTOT       327680

// ---------------- scratch (static device memory; allocation-free) ----------
__device__ float g_hw[(size_t)M1_*CC];       // LN output (tf32-rounded bits)
__device__ float g_qkv[(size_t)M1_*3*CC];    // qkv projections (tf32-rounded)
__device__ float g_o[(size_t)M1_*CC];        // attn out / merged xm (tf32-rounded)
__device__ float g_xres[(size_t)M1_*CC];     // residual stream (fp32, pixel layout)
__device__ float g_fc1[(size_t)M1_*HID_];    // fc1+gelu output (tf32-rounded)
__device__ float g_wt[WTOT];                 // tf32-rounded weights
__device__ float g_bias[64*4*2401];          // combined rpb+mask per (wimg, head)

// ---------------- helpers ----------------
__device__ __forceinline__ uint32_t f2tf32(float x) {
    uint32_t r; asm("cvt.rna.tf32.f32 %0, %1;" : "=r"(r) : "f"(x)); return r;
}
__device__ __forceinline__ float tf32r(float x) { return __uint_as_float(f2tf32(x)); }
__device__ __forceinline__ void mma_tf32(float* c, const uint32_t* a, uint32_t b0, uint32_t b1) {
    asm volatile("mma.sync.aligned.m16n8k8.row.col.f32.tf32.tf32.f32 "
        "{%0,%1,%2,%3}, {%4,%5,%6,%7}, {%8,%9}, {%0,%1,%2,%3};\n"
        : "+f"(c[0]), "+f"(c[1]), "+f"(c[2]), "+f"(c[3])
        : "r"(a[0]), "r"(a[1]), "r"(a[2]), "r"(a[3]), "r"(b0), "r"(b1));
}
__device__ __forceinline__ void ldsm_x4(uint32_t* r, uint32_t saddr) {
    asm volatile("ldmatrix.sync.aligned.m8n8.x4.shared.b16 {%0,%1,%2,%3}, [%4];"
        : "=r"(r[0]), "=r"(r[1]), "=r"(r[2]), "=r"(r[3]) : "r"(saddr));
}
__device__ __forceinline__ void cp_async16(uint32_t saddr, const void* gptr) {
    asm volatile("cp.async.cg.shared.global [%0], [%1], 16;\n" :: "r"(saddr), "l"(gptr));
}
__device__ __forceinline__ void cp_commit() { asm volatile("cp.async.commit_group;\n"); }
__device__ __forceinline__ void cp_wait1() { asm volatile("cp.async.wait_group 1;\n"); }
__device__ __forceinline__ void cp_wait0() { asm volatile("cp.async.wait_group 0;\n"); }

// ---------------- weight pre-round ----------------
__global__ void round_w_kernel(const float* __restrict__ qkv_w, const float* __restrict__ proj_w,
                               const float* __restrict__ fc1_w, const float* __restrict__ fc2_w,
                               const float* __restrict__ merge_w)
{
    int i = blockIdx.x * blockDim.x + threadIdx.x;
    float v;
    if      (i < WOFF_PROJ) v = qkv_w[i];
    else if (i < WOFF_FC1)  v = proj_w[i - WOFF_PROJ];
    else if (i < WOFF_FC2)  v = fc1_w[i - WOFF_FC1];
    else if (i < WOFF_MRG)  v = fc2_w[i - WOFF_FC2];
    else                    v = merge_w[i - WOFF_MRG];
    g_wt[i] = tf32r(v);
}

// ---------------- combined attention bias table: rpb[rel]+mask ------------
__global__ void bias_prep_kernel(const float* __restrict__ rpb,
                                 const int* __restrict__ rel,
                                 const float* __restrict__ mask)
{
    int wimg = blockIdx.x, h = blockIdx.y;
    float* dst = g_bias + ((size_t)wimg*4 + h)*2401;
    const float* msk = mask + (size_t)wimg*2401;
    for (int i = threadIdx.x; i < 2401; i += blockDim.x)
        dst[i] = rpb[rel[i]*4 + h] + msk[i];
}

// ---------------- LN1 + roll(-3,-3) + window partition (tf32-rounded out) --
__global__ void ln1_win_kernel(const float* __restrict__ x,
                               const float* __restrict__ gw,
                               const float* __restrict__ gb)
{
    int warp = (blockIdx.x * blockDim.x + threadIdx.x) >> 5;
    int lane = threadIdx.x & 31;
    int b   = warp / 3136;
    int rem = warp - b * 3136;
    int i = rem / 56;
    int j = rem - i * 56;
    int si = i + 3; if (si >= 56) si -= 56;
    int sj = j + 3; if (sj >= 56) sj -= 56;
    float4 v = *(const float4*)(x + ((((size_t)b*56 + si)*56) + sj)*128 + lane*4);
    float s  = v.x + v.y + v.z + v.w;
    float ss = v.x*v.x + v.y*v.y + v.z*v.z + v.w*v.w;
    #pragma unroll
    for (int o = 16; o; o >>= 1) {
        s  += __shfl_xor_sync(0xffffffffu, s,  o);
        ss += __shfl_xor_sync(0xffffffffu, ss, o);
    }
    float mean = s * (1.0f/128.0f);
    float var  = ss * (1.0f/128.0f) - mean*mean;
    float rstd = rsqrtf(var + 1e-5f);
    float4 wv = *(const float4*)(gw + lane*4);
    float4 bv = *(const float4*)(gb + lane*4);
    float4 o4;
    o4.x = tf32r((v.x - mean)*rstd*wv.x + bv.x);
    o4.y = tf32r((v.y - mean)*rstd*wv.y + bv.y);
    o4.z = tf32r((v.z - mean)*rstd*wv.z + bv.z);
    o4.w = tf32r((v.w - mean)*rstd*wv.w + bv.w);
    int i7 = i / 7, j7 = j / 7;
    int widx = i7*8 + j7;
    int n    = (i - i7*7)*7 + (j - j7*7);
    size_t row = (size_t)(b*64 + widx)*49 + n;
    *(float4*)(g_hw + row*128 + lane*4) = o4;
}

// ---------------- LN2 (pixel layout): g_xres -> g_hw (tf32-rounded) -------
__global__ void ln2_kernel(const float* __restrict__ gw, const float* __restrict__ gb)
{
    int warp = (blockIdx.x * blockDim.x + threadIdx.x) >> 5;
    int lane = threadIdx.x & 31;
    float4 v = *(const float4*)(g_xres + (size_t)warp*128 + lane*4);
    float s  = v.x + v.y + v.z + v.w;
    float ss = v.x*v.x + v.y*v.y + v.z*v.z + v.w*v.w;
    #pragma unroll
    for (int o = 16; o; o >>= 1) {
        s  += __shfl_xor_sync(0xffffffffu, s,  o);
        ss += __shfl_xor_sync(0xffffffffu, ss, o);
    }
    float mean = s * (1.0f/128.0f);
    float var  = ss * (1.0f/128.0f) - mean*mean;
    float rstd = rsqrtf(var + 1e-5f);
    float4 wv = *(const float4*)(gw + lane*4);
    float4 bv = *(const float4*)(gb + lane*4);
    float4 o4;
    o4.x = tf32r((v.x - mean)*rstd*wv.x + bv.x);
    o4.y = tf32r((v.y - mean)*rstd*wv.y + bv.y);
    o4.z = tf32r((v.z - mean)*rstd*wv.z + bv.z);
    o4.w = tf32r((v.w - mean)*rstd*wv.w + bv.w);
    *(float4*)(g_hw + (size_t)warp*128 + lane*4) = o4;
}

// ---------------- patch-merge gather + LN(512): g_xres -> g_o (rounded) ---
__global__ void merge_ln_kernel(const float* __restrict__ gw, const float* __restrict__ gb)
{
    int warp = (blockIdx.x * blockDim.x + threadIdx.x) >> 5;
    int lane = threadIdx.x & 31;
    int b   = warp / 784;
    int rem = warp - b * 784;
    int i2 = rem / 28;
    int j2 = rem - i2 * 28;
    int i0 = 2*i2, j0 = 2*j2;
    const float* p0 = g_xres + (((size_t)b*56 + i0    )*56 + j0    )*128;
    const float* p1 = g_xres + (((size_t)b*56 + i0 + 1)*56 + j0    )*128;
    const float* p2 = g_xres + (((size_t)b*56 + i0    )*56 + j0 + 1)*128;
    const float* p3 = g_xres + (((size_t)b*56 + i0 + 1)*56 + j0 + 1)*128;
    float4 v[4];
    v[0] = *(const float4*)(p0 + lane*4);
    v[1] = *(const float4*)(p1 + lane*4);
    v[2] = *(const float4*)(p2 + lane*4);
    v[3] = *(const float4*)(p3 + lane*4);
    float s = 0.f, ss = 0.f;
    #pragma unroll
    for (int q = 0; q < 4; q++) {
        s  += v[q].x + v[q].y + v[q].z + v[q].w;
        ss += v[q].x*v[q].x + v[q].y*v[q].y + v[q].z*v[q].z + v[q].w*v[q].w;
    }
    #pragma unroll
    for (int o = 16; o; o >>= 1) {
        s  += __shfl_xor_sync(0xffffffffu, s,  o);
        ss += __shfl_xor_sync(0xffffffffu, ss, o);
    }
    float mean = s * (1.0f/512.0f);
    float var  = ss * (1.0f/512.0f) - mean*mean;
    float rstd = rsqrtf(var + 1e-5f);
    float* out = g_o + (size_t)warp*512;
    #pragma unroll
    for (int q = 0; q < 4; q++) {
        int c = q*128 + lane*4;
        float4 wv = *(const float4*)(gw + c);
        float4 bv = *(const float4*)(gb + c);
        float4 o4;
        o4.x = tf32r((v[q].x - mean)*rstd*wv.x + bv.x);
        o4.y = tf32r((v[q].y - mean)*rstd*wv.y + bv.y);
        o4.z = tf32r((v[q].z - mean)*rstd*wv.z + bv.z);
        o4.w = tf32r((v[q].w - mean)*rstd*wv.w + bv.w);
        *(float4*)(out + c) = o4;
    }
}

// ---------------- MMA attention: block = one window, warp = one head ------
#define AQ_STR 132
#define AK_STR 132
#define AV_STR 136
#define AP_STR 60
#define AOFF_K (64*AQ_STR)                  // 8448
#define AOFF_V (AOFF_K + 56*AK_STR)         // 15840
#define AOFF_P (AOFF_V + 56*AV_STR)         // 23456
#define AOFF_I (AOFF_P + 4*16*AP_STR)       // 27296
#define ATT_SMEM ((AOFF_I + 4*16)*4)        // 109440 bytes

__global__ __launch_bounds__(128) void attn_kernel(
    const float* __restrict__ qkv, float* __restrict__ outp)
{
    extern __shared__ float sm[];
    float* qs = sm;
    float* ks = sm + AOFF_K;
    float* vs = sm + AOFF_V;
    const int t    = threadIdx.x;
    const int warp = t >> 5;
    const int lane = t & 31;
    const int win  = blockIdx.x;
    float* Pt   = sm + AOFF_P + warp*16*AP_STR;
    float* invs = sm + AOFF_I + warp*16;

    const float* base = qkv + (size_t)win*49*384;
    for (int idx = t; idx < 49*96; idx += 128) {
        int row = idx / 96;
        int sub = idx - row*96;
        int kind = sub >> 5;
        int c4 = sub & 31;
        float4 v = *(const float4*)(base + (size_t)row*384 + kind*128 + c4*4);
        float* dst = (kind == 0 ? qs + row*AQ_STR :
                      kind == 1 ? ks + row*AK_STR : vs + row*AV_STR) + c4*4;
        *(float4*)dst = v;
    }
    for (int idx = t; idx < 7*AV_STR; idx += 128) {
        int r = idx / AV_STR, c = idx - r*AV_STR;
        vs[(49+r)*AV_STR + c] = 0.f;
        if (c < AK_STR) ks[(49+r)*AK_STR + c] = 0.f;
    }
    __syncthreads();

    const int h   = warp;
    const int qr  = lane >> 2;
    const int qc  = lane & 3;
    const int h32 = h * 32;
    const float* comb = g_bias + (size_t)((win & 63)*4 + h)*2401;
    float* obase = outp + (size_t)win*49*128 + h32;

    for (int mt = 0; mt < 4; mt++) {
        const int r0 = mt*16 + qr;
        const int r1 = r0 + 8;
        float s[7][4];
        #pragma unroll
        for (int jn = 0; jn < 7; jn++)
            #pragma unroll
            for (int c = 0; c < 4; c++) s[jn][c] = 0.f;
        #pragma unroll
        for (int kb = 0; kb < 32; kb += 8) {
            uint32_t a[4];
            a[0] = __float_as_uint(qs[(size_t)r0*AQ_STR + h32 + kb + qc    ]);
            a[1] = __float_as_uint(qs[(size_t)r1*AQ_STR + h32 + kb + qc    ]);
            a[2] = __float_as_uint(qs[(size_t)r0*AQ_STR + h32 + kb + qc + 4]);
            a[3] = __float_as_uint(qs[(size_t)r1*AQ_STR + h32 + kb + qc + 4]);
            #pragma unroll
            for (int jn = 0; jn < 7; jn++) {
                int n0 = jn*8 + qr;
                uint32_t b0 = __float_as_uint(ks[(size_t)n0*AK_STR + h32 + kb + qc    ]);
                uint32_t b1 = __float_as_uint(ks[(size_t)n0*AK_STR + h32 + kb + qc + 4]);
                mma_tf32(s[jn], a, b0, b1);
            }
        }
        const bool v0 = (r0 < 49), v1 = (r1 < 49);
        float mx0 = -1e30f, mx1 = -1e30f;
        #pragma unroll
        for (int jn = 0; jn < 7; jn++) {
            #pragma unroll
            for (int e = 0; e < 2; e++) {
                int col = jn*8 + qc*2 + e;
                if (col < 49) {
                    if (v0) s[jn][e]     += comb[r0*49 + col];
                    if (v1) s[jn][2 + e] += comb[r1*49 + col];
                } else {
                    s[jn][e] = -1e30f; s[jn][2 + e] = -1e30f;
                }
                mx0 = fmaxf(mx0, s[jn][e]);
                mx1 = fmaxf(mx1, s[jn][2 + e]);
            }
        }
        #pragma unroll
        for (int o = 1; o <= 2; o <<= 1) {
            mx0 = fmaxf(mx0, __shfl_xor_sync(0xffffffffu, mx0, o));
            mx1 = fmaxf(mx1, __shfl_xor_sync(0xffffffffu, mx1, o));
        }
        float sum0 = 0.f, sum1 = 0.f;
        #pragma unroll
        for (int jn = 0; jn < 7; jn++) {
            #pragma unroll
            for (int e = 0; e < 2; e++) {
                int col = jn*8 + qc*2 + e;
                float e0 = __expf(s[jn][e]     - mx0);
                float e1 = __expf(s[jn][2 + e] - mx1);
                sum0 += e0; sum1 += e1;
                Pt[qr*AP_STR       + col] = tf32r(e0);
                Pt[(qr + 8)*AP_STR + col] = tf32r(e1);
            }
        }
        #pragma unroll
        for (int o = 1; o <= 2; o <<= 1) {
            sum0 += __shfl_xor_sync(0xffffffffu, sum0, o);
            sum1 += __shfl_xor_sync(0xffffffffu, sum1, o);
        }
        if (qc == 0) {
            invs[qr]     = 1.0f / sum0;
            invs[qr + 8] = 1.0f / sum1;
        }
        __syncwarp();
        float o[4][4];
        #pragma unroll
        for (int jn = 0; jn < 4; jn++)
            #pragma unroll
            for (int c = 0; c < 4; c++) o[jn][c] = 0.f;
        #pragma unroll
        for (int ks2 = 0; ks2 < 7; ks2++) {
            const int kb = ks2*8;
            uint32_t a[4];
            a[0] = __float_as_uint(Pt[qr*AP_STR       + kb + qc    ]);
            a[1] = __float_as_uint(Pt[(qr + 8)*AP_STR + kb + qc    ]);
            a[2] = __float_as_uint(Pt[qr*AP_STR       + kb + qc + 4]);
            a[3] = __float_as_uint(Pt[(qr + 8)*AP_STR + kb + qc + 4]);
            #pragma unroll
            for (int jn = 0; jn < 4; jn++) {
                int n0 = jn*8 + qr;
                uint32_t b0 = __float_as_uint(vs[(size_t)(kb + qc    )*AV_STR + h32 + n0]);
                uint32_t b1 = __float_as_uint(vs[(size_t)(kb + qc + 4)*AV_STR + h32 + n0]);
                mma_tf32(o[jn], a, b0, b1);
            }
        }
        float i0 = invs[qr], i1 = invs[qr + 8];
        #pragma unroll
        for (int jn = 0; jn < 4; jn++) {
            int col = jn*8 + qc*2;
            if (v0) {
                float2 f; f.x = tf32r(o[jn][0]*i0); f.y = tf32r(o[jn][1]*i0);
                *(float2*)(obase + (size_t)r0*128 + col) = f;
            }
            if (v1) {
                float2 f; f.x = tf32r(o[jn][2]*i1); f.y = tf32r(o[jn][3]*i1);
                *(float2*)(obase + (size_t)r1*128 + col) = f;
            }
        }
        __syncwarp();
    }
}

// ---------------- TF32 tensor-core GEMM, cp.async + ldmatrix --------------
// C[M,Nd] = A[M,K] @ W[Nd,K]^T + epilogue. A and W are PRE-ROUNDED to tf32.
// Block tile 128x128, BK=32, 8 warps (4m x 2n), warp tile 32x64 (mf2 x nf8).
// Fragments loaded via ldmatrix.m8n8.x4 (tf32 = 2 b16-matrices per 8x8 f32).
#define TG_STG (128*36*2)           // u32 per stage (A pad 36 + B pad 36)
#define TG_SMEM (TG_STG*2*4)        // bytes, two stages = 73728

template<int EPI>
__global__ __launch_bounds__(256, 2) void tgemm_kernel(
    const float* __restrict__ A, const float* __restrict__ W,
    const float* __restrict__ bias, float* __restrict__ C,
    const float* __restrict__ aux, int M, int Nd, int K)
{
    extern __shared__ __align__(16) uint32_t dsm[];
    const int t    = threadIdx.x;
    const int warp = t >> 5;
    const int lane = t & 31;
    const int qr   = lane >> 2;
    const int qc   = lane & 3;
    const int wm   = warp & 3;    // m warp 0..3
    const int wn   = warp >> 2;   // n warp 0..1
    const int bm   = blockIdx.y * 128;
    const int bn   = blockIdx.x * 128;
    const int row0 = t >> 3;      // 0..31
    const int c4   = t & 7;

    const float* aptr = A + (size_t)(bm + row0)*K + c4*4;
    const float* wptr = W + (size_t)(bn + row0)*K + c4*4;
    const size_t rstr = (size_t)32 * K;

    uint32_t s_a = (uint32_t)__cvta_generic_to_shared(dsm);
    uint32_t s_b = s_a + 128*36*4;

    // per-lane ldmatrix address constant (bytes):
    // row add = (lane&7) + ((lane>>3)&1)*8 ; col add = (lane>>4)*4 words
    const uint32_t laneC = ((((lane & 7) + ((lane >> 3) & 1)*8)*36) + (lane >> 4)*4) * 4;

    float acc[2][8][4] = {};

    const int iters = K >> 5;
    {
        #pragma unroll
        for (int l = 0; l < 4; l++)
            cp_async16(s_a + ((row0 + l*32)*36 + c4*4)*4, aptr + l*rstr);
        #pragma unroll
        for (int l = 0; l < 4; l++)
            cp_async16(s_b + ((row0 + l*32)*36 + c4*4)*4, wptr + l*rstr);
        cp_commit();
    }

    for (int it = 0; it < iters; it++) {
        if (it + 1 < iters) {
            uint32_t sa = s_a + ((it+1)&1)*TG_STG*4;
            uint32_t sb = s_b + ((it+1)&1)*TG_STG*4;
            const float* ap = aptr + (size_t)(it+1)*32;
            const float* wp = wptr + (size_t)(it+1)*32;
            #pragma unroll
            for (int l = 0; l < 4; l++)
                cp_async16(sa + ((row0 + l*32)*36 + c4*4)*4, ap + l*rstr);
            #pragma unroll
            for (int l = 0; l < 4; l++)
                cp_async16(sb + ((row0 + l*32)*36 + c4*4)*4, wp + l*rstr);
            cp_commit();
            cp_wait1();
        } else {
            cp_wait0();
        }
        __syncthreads();

        const uint32_t sA = s_a + (it&1)*TG_STG*4;
        const uint32_t sB = sA + 128*36*4;
        #pragma unroll
        for (int ks = 0; ks < 4; ks++) {
            const int kb = ks * 8;
            uint32_t af[2][4];
            #pragma unroll
            for (int i = 0; i < 2; i++)
                ldsm_x4(af[i], sA + ((wm*32 + i*16)*36 + kb)*4 + laneC);
            #pragma unroll
            for (int p = 0; p < 4; p++) {
                uint32_t bf[4];   // bf[0]=b0(t2p) bf[1]=b0(t2p+1) bf[2]=b1(t2p) bf[3]=b1(t2p+1)
                ldsm_x4(bf, sB + ((wn*64 + p*16)*36 + kb)*4 + laneC);
                mma_tf32(acc[0][2*p    ], af[0], bf[0], bf[2]);
                mma_tf32(acc[1][2*p    ], af[1], bf[0], bf[2]);
                mma_tf32(acc[0][2*p + 1], af[0], bf[1], bf[3]);
                mma_tf32(acc[1][2*p + 1], af[1], bf[1], bf[3]);
            }
        }
        __syncthreads();
    }

    // ---- epilogue ----
    #pragma unroll
    for (int i = 0; i < 2; i++) {
        #pragma unroll
        for (int half = 0; half < 2; half++) {
            const int m = bm + wm*32 + i*16 + qr + half*8;
            size_t obase;
            if (EPI == 2) {
                int win = m / 49, nn = m - win*49;
                int bb = win >> 6, w = win & 63;
                int n7 = nn / 7;
                int pi = (w >> 3)*7 + n7;
                int pj = (w & 7)*7 + (nn - n7*7);
                int ii = pi + 3; if (ii >= 56) ii -= 56;
                int jj = pj + 3; if (jj >= 56) jj -= 56;
                obase = (((size_t)bb*56 + ii)*56 + jj)*128;
            } else {
                obase = (size_t)m * Nd;
            }
            #pragma unroll
            for (int j = 0; j < 8; j++) {
                const int n = bn + wn*64 + j*8 + qc*2;
                #pragma unroll
                for (int e = 0; e < 2; e++) {
                    const int nc = n + e;
                    float v = acc[i][j][half*2 + e];
                    if (EPI == 0) {
                        if (bias) v += bias[nc];
                        C[obase + nc] = v;
                    } else if (EPI == 1) {
                        v += bias[nc];
                        if (nc < 128) v *= 0.17677669529663687f;   // 1/sqrt(32)
                        C[obase + nc] = tf32r(v);
                    } else if (EPI == 2) {
                        v += bias[nc];
                        C[obase + nc] = v + aux[obase + nc];
                    } else if (EPI == 3) {
                        v += bias[nc];
                        C[obase + nc] = tf32r(0.5f * v * (1.0f + erff(v * 0.70710678118654752f)));
                    } else { // EPI == 4
                        v += bias[nc];
                        C[obase + nc] = v + aux[obase + nc];
                    }
                }
            }
        }
    }
}

// ---------------- launcher ----------------
extern "C" void kernel_launch(void* const* d_in, const int* in_sizes, int n_in,
                              void* d_out, int out_size)
{
    const float* x       = (const float*)d_in[0];
    const float* n1w     = (const float*)d_in[1];
    const float* n1b     = (const float*)d_in[2];
    const float* qkv_w   = (const float*)d_in[3];
    const float* qkv_b   = (const float*)d_in[4];
    const float* proj_w  = (const float*)d_in[5];
    const float* proj_b  = (const float*)d_in[6];
    const float* rpb     = (const float*)d_in[7];
    const float* n2w     = (const float*)d_in[8];
    const float* n2b     = (const float*)d_in[9];
    const float* fc1_w   = (const float*)d_in[10];
    const float* fc1_b   = (const float*)d_in[11];
    const float* fc2_w   = (const float*)d_in[12];
    const float* fc2_b   = (const float*)d_in[13];
    const float* mnw     = (const float*)d_in[14];
    const float* mnb     = (const float*)d_in[15];
    const float* merge_w = (const float*)d_in[16];
    const int*   rel_idx = (const int*)d_in[17];
    const float* amask   = (const float*)d_in[18];
    float* out = (float*)d_out;

    float *hw, *qkv, *o, *xres, *fc1, *wt;
    cudaGetSymbolAddress((void**)&hw,   g_hw);
    cudaGetSymbolAddress((void**)&qkv,  g_qkv);
    cudaGetSymbolAddress((void**)&o,    g_o);
    cudaGetSymbolAddress((void**)&xres, g_xres);
    cudaGetSymbolAddress((void**)&fc1,  g_fc1);
    cudaGetSymbolAddress((void**)&wt,   g_wt);

    cudaFuncSetAttribute(tgemm_kernel<0>, cudaFuncAttributeMaxDynamicSharedMemorySize, TG_SMEM);
    cudaFuncSetAttribute(tgemm_kernel<1>, cudaFuncAttributeMaxDynamicSharedMemorySize, TG_SMEM);
    cudaFuncSetAttribute(tgemm_kernel<2>, cudaFuncAttributeMaxDynamicSharedMemorySize, TG_SMEM);
    cudaFuncSetAttribute(tgemm_kernel<3>, cudaFuncAttributeMaxDynamicSharedMemorySize, TG_SMEM);
    cudaFuncSetAttribute(tgemm_kernel<4>, cudaFuncAttributeMaxDynamicSharedMemorySize, TG_SMEM);
    cudaFuncSetAttribute(attn_kernel, cudaFuncAttributeMaxDynamicSharedMemorySize, ATT_SMEM);

    // 0. pre-round weights; build combined attention bias table
    round_w_kernel<<<WTOT/256, 256>>>(qkv_w, proj_w, fc1_w, fc2_w, merge_w);
    bias_prep_kernel<<<dim3(64, 4), 256>>>(rpb, rel_idx, amask);
    // 1. LN1 + roll + window partition (rounded)
    ln1_win_kernel<<<PIX/8, 256>>>(x, n1w, n1b);
    // 2. qkv GEMM (scale folded into q; rounded out)
    tgemm_kernel<1><<<dim3(3, M1_/128), 256, TG_SMEM>>>(hw, wt + WOFF_QKV, qkv_b, qkv, nullptr, M1_, 384, 128);
    // 3. windowed attention (tensor cores; rounded out)
    attn_kernel<<<4096, 128, ATT_SMEM>>>(qkv, o);
    // 4. proj GEMM + window-reverse + roll-back + residual -> xres (pixel layout)
    tgemm_kernel<2><<<dim3(1, M1_/128), 256, TG_SMEM>>>(o, wt + WOFF_PROJ, proj_b, xres, x, M1_, 128, 128);
    // 5. LN2: xres -> g_hw (rounded)
    ln2_kernel<<<PIX/8, 256>>>(n2w, n2b);
    // 6. fc1 GEMM + GELU (rounded out)
    tgemm_kernel<3><<<dim3(4, M1_/128), 256, TG_SMEM>>>(hw, wt + WOFF_FC1, fc1_b, fc1, nullptr, M1_, 512, 128);
    // 7. fc2 GEMM + residual (in place on xres)
    tgemm_kernel<4><<<dim3(1, M1_/128), 256, TG_SMEM>>>(fc1, wt + WOFF_FC2, fc2_b, xres, xres, M1_, 128, 512);
    // 8. patch-merge gather + LN(512): xres -> g_o (rounded, reuse as xm)
    merge_ln_kernel<<<M2_/8, 256>>>(mnw, mnb);
    // 9. merge GEMM -> output
    tgemm_kernel<0><<<dim3(2, M2_/128), 256, TG_SMEM>>>(o, wt + WOFF_MRG, nullptr, out, nullptr, M2_, 256, 512);
}